// round 2
// baseline (speedup 1.0000x reference)
#include <cuda_runtime.h>
#include <cuda_bf16.h>
#include <math.h>

// Problem dims
#define Bb 2
#define Nn 2048
#define Ff 1024
#define Hh 16
#define Dd 64
#define OUTN 4194304ULL          /* B*N*H*D  : start of kv region in d_out */
#define KVPLANE 131072ULL        /* N*D per (b,h) plane */
#define LDT 20                   /* padded stride (in uint32 pairs) for bf16x2 tiles */

// Scratch (static device globals)
__device__ float g_S[(size_t)Bb * Hh * Nn * Nn];   // 512 MB scores/attn [b][h][i][j]
__device__ float g_Q[(size_t)Bb * Hh * Nn * Dd];   // q (pre-scaled) [b][h][n][d]
__device__ float g_O[(size_t)Bb * Nn * Hh * Dd];   // attn@v, [b][n][h][d]

// ---------------------------------------------------------------------------
// helpers: bf16 2-term split + packed mma
// ---------------------------------------------------------------------------
__device__ __forceinline__ void split_pack(float x0, float x1,
                                           unsigned &hi, unsigned &lo)
{
    __nv_bfloat16 h0 = __float2bfloat16(x0), h1 = __float2bfloat16(x1);
    float f0 = __bfloat162float(h0), f1 = __bfloat162float(h1);
    __nv_bfloat16 l0 = __float2bfloat16(x0 - f0), l1 = __float2bfloat16(x1 - f1);
    hi = ((unsigned)__bfloat16_as_ushort(h1) << 16) | (unsigned)__bfloat16_as_ushort(h0);
    lo = ((unsigned)__bfloat16_as_ushort(l1) << 16) | (unsigned)__bfloat16_as_ushort(l0);
}

__device__ __forceinline__ void mma_bf16(float c[4],
                                         unsigned a0, unsigned a1, unsigned a2, unsigned a3,
                                         unsigned b0, unsigned b1)
{
    asm volatile(
        "mma.sync.aligned.m16n8k16.row.col.f32.bf16.bf16.f32 "
        "{%0,%1,%2,%3},{%4,%5,%6,%7},{%8,%9},{%0,%1,%2,%3};\n"
        : "+f"(c[0]), "+f"(c[1]), "+f"(c[2]), "+f"(c[3])
        : "r"(a0), "r"(a1), "r"(a2), "r"(a3), "r"(b0), "r"(b1));
}

// ---------------------------------------------------------------------------
// Kernel 1: QKV projection (tensor-core, 2-term bf16).
//   C[m,r] = sum_k x[m,k] * wqkv[r,k];  M=4096, N=3072, K=1024.
//   Scatter: r = h*192 + d*3 + c;  q->g_Q (x0.125), k/v -> d_out kv region.
// ---------------------------------------------------------------------------
__global__ __launch_bounds__(256) void k_qkv(const float* __restrict__ x,
                                             const float* __restrict__ wqkv,
                                             float* __restrict__ out)
{
    __shared__ unsigned Ah[128][LDT], Al[128][LDT], Bh[128][LDT], Bl[128][LDT];
    const int t = threadIdx.x, warp = t >> 5, lane = t & 31;
    const int wm = warp >> 2, wn = warp & 3;
    const int g = lane >> 2, q = lane & 3;
    const int m0 = blockIdx.y * 128, n0 = blockIdx.x * 128;

    float acc[4][4][4];
#pragma unroll
    for (int i = 0; i < 4; i++)
#pragma unroll
        for (int j = 0; j < 4; j++)
#pragma unroll
            for (int c = 0; c < 4; c++) acc[i][j][c] = 0.f;

    for (int kt = 0; kt < 1024; kt += 32) {
#pragma unroll
        for (int i = 0; i < 4; i++) {
            int idx = t + i * 256;
            int row = idx >> 3;
            int c4  = (idx & 7) * 4;
            float4 va = *(const float4*)(x + (size_t)(m0 + row) * 1024 + kt + c4);
            unsigned h0, l0, h1, l1;
            split_pack(va.x, va.y, h0, l0);
            split_pack(va.z, va.w, h1, l1);
            Ah[row][c4 / 2] = h0; Ah[row][c4 / 2 + 1] = h1;
            Al[row][c4 / 2] = l0; Al[row][c4 / 2 + 1] = l1;
            float4 vb = *(const float4*)(wqkv + (size_t)(n0 + row) * 1024 + kt + c4);
            split_pack(vb.x, vb.y, h0, l0);
            split_pack(vb.z, vb.w, h1, l1);
            Bh[row][c4 / 2] = h0; Bh[row][c4 / 2 + 1] = h1;
            Bl[row][c4 / 2] = l0; Bl[row][c4 / 2 + 1] = l1;
        }
        __syncthreads();
#pragma unroll
        for (int ks = 0; ks < 2; ks++) {
            int kc = ks * 8;
            unsigned ah[4][4], al[4][4];
#pragma unroll
            for (int mi = 0; mi < 4; mi++) {
                int mr = wm * 64 + mi * 16 + g;
                ah[mi][0] = Ah[mr][kc + q];     ah[mi][1] = Ah[mr + 8][kc + q];
                ah[mi][2] = Ah[mr][kc + q + 4]; ah[mi][3] = Ah[mr + 8][kc + q + 4];
                al[mi][0] = Al[mr][kc + q];     al[mi][1] = Al[mr + 8][kc + q];
                al[mi][2] = Al[mr][kc + q + 4]; al[mi][3] = Al[mr + 8][kc + q + 4];
            }
#pragma unroll
            for (int ni = 0; ni < 4; ni++) {
                int nr = wn * 32 + ni * 8 + g;
                unsigned bh0 = Bh[nr][kc + q], bh1 = Bh[nr][kc + q + 4];
                unsigned bl0 = Bl[nr][kc + q], bl1 = Bl[nr][kc + q + 4];
#pragma unroll
                for (int mi = 0; mi < 4; mi++) {
                    mma_bf16(acc[mi][ni], ah[mi][0], ah[mi][1], ah[mi][2], ah[mi][3], bh0, bh1);
                    mma_bf16(acc[mi][ni], ah[mi][0], ah[mi][1], ah[mi][2], ah[mi][3], bl0, bl1);
                    mma_bf16(acc[mi][ni], al[mi][0], al[mi][1], al[mi][2], al[mi][3], bh0, bh1);
                }
            }
        }
        __syncthreads();
    }

#pragma unroll
    for (int mi = 0; mi < 4; mi++) {
#pragma unroll
        for (int cc = 0; cc < 2; cc++) {
            int m  = m0 + wm * 64 + mi * 16 + g + cc * 8;
            int bb = m >> 11;
            int n  = m & 2047;
#pragma unroll
            for (int ni = 0; ni < 4; ni++) {
#pragma unroll
                for (int e = 0; e < 2; e++) {
                    int r = n0 + wn * 32 + ni * 8 + q * 2 + e;
                    float v = acc[mi][ni][cc * 2 + e];
                    int h = r / 192, rem = r - h * 192;
                    int d = rem / 3,  c = rem - d * 3;
                    if (c == 0) {
                        g_Q[(((size_t)(bb * 16 + h)) * 2048 + n) * 64 + d] = v * 0.125f;
                    } else {
                        out[OUTN + (((size_t)((c - 1) * 2 + bb) * 16 + h) * 2048 + n) * 64 + d] = v;
                    }
                }
            }
        }
    }
}

// ---------------------------------------------------------------------------
// Kernel 2: scores per (b,h). S = Q @ K^T, K-dim = 64. Output g_S fp32.
// ---------------------------------------------------------------------------
__global__ __launch_bounds__(256) void k_scores(const float* __restrict__ out)
{
    __shared__ unsigned Ah[128][LDT], Al[128][LDT], Bh[128][LDT], Bl[128][LDT];
    const int t = threadIdx.x, warp = t >> 5, lane = t & 31;
    const int wm = warp >> 2, wn = warp & 3;
    const int g = lane >> 2, q = lane & 3;
    const int bh = blockIdx.z;
    const int m0 = blockIdx.y * 128, n0 = blockIdx.x * 128;

    const float* Q = g_Q + (size_t)bh * 2048 * 64;
    const float* K = out + OUTN + (size_t)bh * KVPLANE;

    float acc[4][4][4];
#pragma unroll
    for (int i = 0; i < 4; i++)
#pragma unroll
        for (int j = 0; j < 4; j++)
#pragma unroll
            for (int c = 0; c < 4; c++) acc[i][j][c] = 0.f;

    for (int kt = 0; kt < 64; kt += 32) {
#pragma unroll
        for (int i = 0; i < 4; i++) {
            int idx = t + i * 256;
            int row = idx >> 3;
            int c4  = (idx & 7) * 4;
            float4 va = *(const float4*)(Q + (size_t)(m0 + row) * 64 + kt + c4);
            unsigned h0, l0, h1, l1;
            split_pack(va.x, va.y, h0, l0);
            split_pack(va.z, va.w, h1, l1);
            Ah[row][c4 / 2] = h0; Ah[row][c4 / 2 + 1] = h1;
            Al[row][c4 / 2] = l0; Al[row][c4 / 2 + 1] = l1;
            float4 vb = *(const float4*)(K + (size_t)(n0 + row) * 64 + kt + c4);
            split_pack(vb.x, vb.y, h0, l0);
            split_pack(vb.z, vb.w, h1, l1);
            Bh[row][c4 / 2] = h0; Bh[row][c4 / 2 + 1] = h1;
            Bl[row][c4 / 2] = l0; Bl[row][c4 / 2 + 1] = l1;
        }
        __syncthreads();
#pragma unroll
        for (int ks = 0; ks < 2; ks++) {
            int kc = ks * 8;
            unsigned ah[4][4], al[4][4];
#pragma unroll
            for (int mi = 0; mi < 4; mi++) {
                int mr = wm * 64 + mi * 16 + g;
                ah[mi][0] = Ah[mr][kc + q];     ah[mi][1] = Ah[mr + 8][kc + q];
                ah[mi][2] = Ah[mr][kc + q + 4]; ah[mi][3] = Ah[mr + 8][kc + q + 4];
                al[mi][0] = Al[mr][kc + q];     al[mi][1] = Al[mr + 8][kc + q];
                al[mi][2] = Al[mr][kc + q + 4]; al[mi][3] = Al[mr + 8][kc + q + 4];
            }
#pragma unroll
            for (int ni = 0; ni < 4; ni++) {
                int nr = wn * 32 + ni * 8 + g;
                unsigned bh0 = Bh[nr][kc + q], bh1 = Bh[nr][kc + q + 4];
                unsigned bl0 = Bl[nr][kc + q], bl1 = Bl[nr][kc + q + 4];
#pragma unroll
                for (int mi = 0; mi < 4; mi++) {
                    mma_bf16(acc[mi][ni], ah[mi][0], ah[mi][1], ah[mi][2], ah[mi][3], bh0, bh1);
                    mma_bf16(acc[mi][ni], ah[mi][0], ah[mi][1], ah[mi][2], ah[mi][3], bl0, bl1);
                    mma_bf16(acc[mi][ni], al[mi][0], al[mi][1], al[mi][2], al[mi][3], bh0, bh1);
                }
            }
        }
        __syncthreads();
    }

#pragma unroll
    for (int mi = 0; mi < 4; mi++) {
#pragma unroll
        for (int cc = 0; cc < 2; cc++) {
            int m = m0 + wm * 64 + mi * 16 + g + cc * 8;
            float* Sp = g_S + ((size_t)bh * 2048 + m) * 2048;
#pragma unroll
            for (int ni = 0; ni < 4; ni++) {
                int n = n0 + wn * 32 + ni * 8 + q * 2;
                float2 v = make_float2(acc[mi][ni][cc * 2], acc[mi][ni][cc * 2 + 1]);
                *(float2*)(Sp + n) = v;
            }
        }
    }
}

// ---------------------------------------------------------------------------
// Kernel 3: fused premix + softmax + postmix. One CTA per (b, i).
// 1024 threads; 16x2048 fp32 row block in dynamic smem.
// ---------------------------------------------------------------------------
__global__ __launch_bounds__(1024) void k_mix(const float* __restrict__ wpre,
                                              const float* __restrict__ bpre,
                                              const float* __restrict__ wpost,
                                              const float* __restrict__ bpost)
{
    extern __shared__ float sm[];
    float* S   = sm;                // 16*2048
    float* Wa  = sm + 16 * 2048;    // 256
    float* Wb  = Wa + 256;          // 256
    float* ba  = Wb + 256;          // 16
    float* bb2 = ba + 16;           // 16

    const int t  = threadIdx.x;
    const int bi = blockIdx.x;
    const int b  = bi >> 11;
    const int i  = bi & 2047;

    if (t < 256) { Wa[t] = wpre[t]; Wb[t] = wpost[t]; }
    if (t < 16)  { ba[t] = bpre[t]; bb2[t] = bpost[t]; }

    for (int h = 0; h < 16; h++) {
        const float* src = g_S + (((size_t)(b * 16 + h)) * 2048 + i) * 2048;
        float* dst = S + h * 2048;
        for (int j = t * 4; j < 2048; j += 4096)
            *(float4*)(dst + j) = *(const float4*)(src + j);
    }
    __syncthreads();

    // premix
    for (int j = t; j < 2048; j += 1024) {
        float sv[16];
#pragma unroll
        for (int h = 0; h < 16; h++) sv[h] = S[h * 2048 + j];
#pragma unroll
        for (int gg = 0; gg < 16; gg++) {
            float a = ba[gg];
#pragma unroll
            for (int h = 0; h < 16; h++) a += Wa[gg * 16 + h] * sv[h];
            S[gg * 2048 + j] = a;
        }
    }
    __syncthreads();

    // softmax: warps 0..15 each own one head row
    const int w = t >> 5, lane = t & 31;
    if (w < 16) {
        float* row = S + w * 2048;
        float m = -1e30f;
        for (int j = lane; j < 2048; j += 32) m = fmaxf(m, row[j]);
#pragma unroll
        for (int o = 16; o; o >>= 1) m = fmaxf(m, __shfl_xor_sync(0xffffffffu, m, o));
        float z = 0.f;
        for (int j = lane; j < 2048; j += 32) {
            float e = expf(row[j] - m);
            row[j] = e;
            z += e;
        }
#pragma unroll
        for (int o = 16; o; o >>= 1) z += __shfl_xor_sync(0xffffffffu, z, o);
        float inv = 1.f / z;
        for (int j = lane; j < 2048; j += 32) row[j] *= inv;
    }
    __syncthreads();

    // postmix, write back
    for (int j = t; j < 2048; j += 1024) {
        float sv[16];
#pragma unroll
        for (int h = 0; h < 16; h++) sv[h] = S[h * 2048 + j];
#pragma unroll
        for (int gg = 0; gg < 16; gg++) {
            float a = bb2[gg];
#pragma unroll
            for (int h = 0; h < 16; h++) a += Wb[gg * 16 + h] * sv[h];
            g_S[(((size_t)(b * 16 + gg)) * 2048 + i) * 2048 + j] = a;
        }
    }
}

// ---------------------------------------------------------------------------
// Kernel 4: AV per (b,h). O = P(2048x2048) @ V(2048x64), tensor-core 2-term.
// ---------------------------------------------------------------------------
__global__ __launch_bounds__(256) void k_av(const float* __restrict__ out)
{
    __shared__ unsigned Ah[128][LDT], Al[128][LDT];
    __shared__ unsigned Bh[64][LDT], Bl[64][LDT];
    const int t = threadIdx.x, warp = t >> 5, lane = t & 31;
    const int g = lane >> 2, q = lane & 3;
    const int bh = blockIdx.z;
    const int m0 = blockIdx.y * 128;

    const float* P = g_S + (size_t)bh * 2048 * 2048;
    const float* V = out + OUTN + ((size_t)(bh + 32)) * KVPLANE;

    float acc[8][4];
#pragma unroll
    for (int i = 0; i < 8; i++)
#pragma unroll
        for (int c = 0; c < 4; c++) acc[i][c] = 0.f;

    for (int kt = 0; kt < 2048; kt += 32) {
        // A tile 128x32 (P rows)
#pragma unroll
        for (int i = 0; i < 4; i++) {
            int idx = t + i * 256;
            int row = idx >> 3;
            int c4  = (idx & 7) * 4;
            float4 va = *(const float4*)(P + (size_t)(m0 + row) * 2048 + kt + c4);
            unsigned h0, l0, h1, l1;
            split_pack(va.x, va.y, h0, l0);
            split_pack(va.z, va.w, h1, l1);
            Ah[row][c4 / 2] = h0; Ah[row][c4 / 2 + 1] = h1;
            Al[row][c4 / 2] = l0; Al[row][c4 / 2 + 1] = l1;
        }
        // V tile 32x64 -> transposed packed pairs Bs[n][k/2]
#pragma unroll
        for (int i = 0; i < 4; i++) {
            int p  = t + i * 256;       // pair index 0..1023
            int n  = p & 63;
            int kp = p >> 6;            // 0..15
            float v0 = V[(size_t)(kt + 2 * kp)     * 64 + n];
            float v1 = V[(size_t)(kt + 2 * kp + 1) * 64 + n];
            unsigned h, l;
            split_pack(v0, v1, h, l);
            Bh[n][kp] = h;
            Bl[n][kp] = l;
        }
        __syncthreads();
#pragma unroll
        for (int ks = 0; ks < 2; ks++) {
            int kc = ks * 8;
            int mr = warp * 16 + g;
            unsigned a0 = Ah[mr][kc + q],     a1 = Ah[mr + 8][kc + q];
            unsigned a2 = Ah[mr][kc + q + 4], a3 = Ah[mr + 8][kc + q + 4];
            unsigned c0 = Al[mr][kc + q],     c1 = Al[mr + 8][kc + q];
            unsigned c2 = Al[mr][kc + q + 4], c3 = Al[mr + 8][kc + q + 4];
#pragma unroll
            for (int ni = 0; ni < 8; ni++) {
                int nr = ni * 8 + g;
                unsigned bh0 = Bh[nr][kc + q], bh1 = Bh[nr][kc + q + 4];
                unsigned bl0 = Bl[nr][kc + q], bl1 = Bl[nr][kc + q + 4];
                mma_bf16(acc[ni], a0, a1, a2, a3, bh0, bh1);
                mma_bf16(acc[ni], a0, a1, a2, a3, bl0, bl1);
                mma_bf16(acc[ni], c0, c1, c2, c3, bh0, bh1);
            }
        }
        __syncthreads();
    }

    const int b = bh >> 4, h = bh & 15;
#pragma unroll
    for (int ni = 0; ni < 8; ni++) {
        int n = ni * 8 + q * 2;
        int m = m0 + warp * 16 + g;
        *(float2*)(g_O + (((size_t)b * 2048 + m) * 16 + h) * 64 + n) =
            make_float2(acc[ni][0], acc[ni][1]);
        *(float2*)(g_O + (((size_t)b * 2048 + m + 8) * 16 + h) * 64 + n) =
            make_float2(acc[ni][2], acc[ni][3]);
    }
}

// ---------------------------------------------------------------------------
// Kernel 5: output projection. M=4096, N=1024, K=1024 (tensor-core 2-term).
// ---------------------------------------------------------------------------
__global__ __launch_bounds__(256) void k_out(const float* __restrict__ wout,
                                             float* __restrict__ out)
{
    __shared__ unsigned Ah[128][LDT], Al[128][LDT], Bh[128][LDT], Bl[128][LDT];
    const int t = threadIdx.x, warp = t >> 5, lane = t & 31;
    const int wm = warp >> 2, wn = warp & 3;
    const int g = lane >> 2, q = lane & 3;
    const int m0 = blockIdx.y * 128, n0 = blockIdx.x * 128;

    float acc[4][4][4];
#pragma unroll
    for (int i = 0; i < 4; i++)
#pragma unroll
        for (int j = 0; j < 4; j++)
#pragma unroll
            for (int c = 0; c < 4; c++) acc[i][j][c] = 0.f;

    for (int kt = 0; kt < 1024; kt += 32) {
#pragma unroll
        for (int i = 0; i < 4; i++) {
            int idx = t + i * 256;
            int row = idx >> 3;
            int c4  = (idx & 7) * 4;
            float4 va = *(const float4*)(g_O + (size_t)(m0 + row) * 1024 + kt + c4);
            unsigned h0, l0, h1, l1;
            split_pack(va.x, va.y, h0, l0);
            split_pack(va.z, va.w, h1, l1);
            Ah[row][c4 / 2] = h0; Ah[row][c4 / 2 + 1] = h1;
            Al[row][c4 / 2] = l0; Al[row][c4 / 2 + 1] = l1;
            float4 vb = *(const float4*)(wout + (size_t)(n0 + row) * 1024 + kt + c4);
            split_pack(vb.x, vb.y, h0, l0);
            split_pack(vb.z, vb.w, h1, l1);
            Bh[row][c4 / 2] = h0; Bh[row][c4 / 2 + 1] = h1;
            Bl[row][c4 / 2] = l0; Bl[row][c4 / 2 + 1] = l1;
        }
        __syncthreads();
#pragma unroll
        for (int ks = 0; ks < 2; ks++) {
            int kc = ks * 8;
            unsigned ah[4][4], al[4][4];
#pragma unroll
            for (int mi = 0; mi < 4; mi++) {
                int mr = wm * 64 + mi * 16 + g;
                ah[mi][0] = Ah[mr][kc + q];     ah[mi][1] = Ah[mr + 8][kc + q];
                ah[mi][2] = Ah[mr][kc + q + 4]; ah[mi][3] = Ah[mr + 8][kc + q + 4];
                al[mi][0] = Al[mr][kc + q];     al[mi][1] = Al[mr + 8][kc + q];
                al[mi][2] = Al[mr][kc + q + 4]; al[mi][3] = Al[mr + 8][kc + q + 4];
            }
#pragma unroll
            for (int ni = 0; ni < 4; ni++) {
                int nr = wn * 32 + ni * 8 + g;
                unsigned bh0 = Bh[nr][kc + q], bh1 = Bh[nr][kc + q + 4];
                unsigned bl0 = Bl[nr][kc + q], bl1 = Bl[nr][kc + q + 4];
#pragma unroll
                for (int mi = 0; mi < 4; mi++) {
                    mma_bf16(acc[mi][ni], ah[mi][0], ah[mi][1], ah[mi][2], ah[mi][3], bh0, bh1);
                    mma_bf16(acc[mi][ni], ah[mi][0], ah[mi][1], ah[mi][2], ah[mi][3], bl0, bl1);
                    mma_bf16(acc[mi][ni], al[mi][0], al[mi][1], al[mi][2], al[mi][3], bh0, bh1);
                }
            }
        }
        __syncthreads();
    }

#pragma unroll
    for (int mi = 0; mi < 4; mi++) {
#pragma unroll
        for (int cc = 0; cc < 2; cc++) {
            int m = m0 + wm * 64 + mi * 16 + g + cc * 8;
            float* Op = out + (size_t)m * 1024;
#pragma unroll
            for (int ni = 0; ni < 4; ni++) {
                int n = n0 + wn * 32 + ni * 8 + q * 2;
                *(float2*)(Op + n) = make_float2(acc[mi][ni][cc * 2],
                                                 acc[mi][ni][cc * 2 + 1]);
            }
        }
    }
}

// ---------------------------------------------------------------------------
extern "C" void kernel_launch(void* const* d_in, const int* in_sizes, int n_in,
                              void* d_out, int out_size)
{
    const float* x     = (const float*)d_in[0];
    const float* wqkv  = (const float*)d_in[1];
    const float* wout  = (const float*)d_in[2];
    const float* wpre  = (const float*)d_in[3];
    const float* bpre  = (const float*)d_in[4];
    const float* wpost = (const float*)d_in[5];
    const float* bpost = (const float*)d_in[6];
    float* out = (float*)d_out;

    k_qkv<<<dim3(24, 32), 256>>>(x, wqkv, out);

    k_scores<<<dim3(16, 16, 32), 256>>>(out);

    const int SM3 = (16 * 2048 + 544) * 4;  // 133,248 B dynamic smem
    cudaFuncSetAttribute(k_mix, cudaFuncAttributeMaxDynamicSharedMemorySize, SM3);
    k_mix<<<Bb * Nn, 1024, SM3>>>(wpre, bpre, wpost, bpost);

    k_av<<<dim3(1, 16, 32), 256>>>(out);

    k_out<<<dim3(8, 32), 256>>>(wout, out);
}

// round 3
// speedup vs baseline: 2.8912x; 2.8912x over previous
#include <cuda_runtime.h>
#include <cuda_bf16.h>
#include <math.h>

// dims: B=2 N=2048 F=1024 H=16 D=64
#define OUTN 4194304ULL            /* start of kv region in d_out */
#define KV1  (OUTN + 4194304ULL)   /* start of kv[1] (v) */

// fp32 scratch
__device__ float g_S[(size_t)32 * 2048 * 2048];   // scores [bh][i][j]
__device__ float g_Q[(size_t)32 * 2048 * 64];     // q (pre-scaled)

// packed bf16x2 planes (pairs along the contraction dim)
__device__ unsigned g_xh[4096 * 512],  g_xl[4096 * 512];
__device__ unsigned g_wqh[3072 * 512], g_wql[3072 * 512];
__device__ unsigned g_woh[1024 * 512], g_wol[1024 * 512];
__device__ unsigned g_qh[32 * 2048 * 32], g_ql[32 * 2048 * 32];
__device__ unsigned g_kh[32 * 2048 * 32], g_kl[32 * 2048 * 32];
__device__ unsigned g_vth[32 * 64 * 1024], g_vtl[32 * 64 * 1024];
__device__ unsigned g_ph[(size_t)32 * 2048 * 1024], g_pl[(size_t)32 * 2048 * 1024];
__device__ unsigned g_oh[4096 * 512], g_ol[4096 * 512];

// ---------------------------------------------------------------------------
__device__ __forceinline__ void split_pack(float x0, float x1,
                                           unsigned &hi, unsigned &lo)
{
    __nv_bfloat16 h0 = __float2bfloat16(x0), h1 = __float2bfloat16(x1);
    float f0 = __bfloat162float(h0), f1 = __bfloat162float(h1);
    __nv_bfloat16 l0 = __float2bfloat16(x0 - f0), l1 = __float2bfloat16(x1 - f1);
    hi = ((unsigned)__bfloat16_as_ushort(h1) << 16) | (unsigned)__bfloat16_as_ushort(h0);
    lo = ((unsigned)__bfloat16_as_ushort(l1) << 16) | (unsigned)__bfloat16_as_ushort(l0);
}

__device__ __forceinline__ void mma_bf16(float c[4],
                                         unsigned a0, unsigned a1, unsigned a2, unsigned a3,
                                         unsigned b0, unsigned b1)
{
    asm volatile(
        "mma.sync.aligned.m16n8k16.row.col.f32.bf16.bf16.f32 "
        "{%0,%1,%2,%3},{%4,%5,%6,%7},{%8,%9},{%0,%1,%2,%3};\n"
        : "+f"(c[0]), "+f"(c[1]), "+f"(c[2]), "+f"(c[3])
        : "r"(a0), "r"(a1), "r"(a2), "r"(a3), "r"(b0), "r"(b1));
}

__device__ __forceinline__ void cpa(unsigned dst, const unsigned* src)
{
    asm volatile("cp.async.cg.shared.global [%0], [%1], 16;" :: "r"(dst), "l"(src));
}
#define CP_COMMIT asm volatile("cp.async.commit_group;")
#define CP_WAIT0  asm volatile("cp.async.wait_group 0;")

// ---------------------------------------------------------------------------
// pack input tensors: x (2M pairs), wqkv (1.5M), wout (0.5M)
// ---------------------------------------------------------------------------
__global__ __launch_bounds__(256) void k_pack_in(const float* __restrict__ x,
                                                 const float* __restrict__ wq,
                                                 const float* __restrict__ wo)
{
    unsigned i = blockIdx.x * 256 + threadIdx.x;
    unsigned h, l;
    if (i < 2097152u) {
        float2 v = ((const float2*)x)[i];
        split_pack(v.x, v.y, h, l); g_xh[i] = h; g_xl[i] = l;
    } else if (i < 3670016u) {
        unsigned j = i - 2097152u;
        float2 v = ((const float2*)wq)[j];
        split_pack(v.x, v.y, h, l); g_wqh[j] = h; g_wql[j] = l;
    } else if (i < 4194304u) {
        unsigned j = i - 3670016u;
        float2 v = ((const float2*)wo)[j];
        split_pack(v.x, v.y, h, l); g_woh[j] = h; g_wol[j] = l;
    }
}

// ---------------------------------------------------------------------------
// pack q (from g_Q), k (from d_out kv0), v-transposed (from d_out kv1)
// ---------------------------------------------------------------------------
__global__ __launch_bounds__(256) void k_pack_qkv(const float* __restrict__ out)
{
    unsigned i = blockIdx.x * 256 + threadIdx.x;   // 0 .. 6291455
    unsigned h, l;
    if (i < 2097152u) {
        float2 v = ((const float2*)g_Q)[i];
        split_pack(v.x, v.y, h, l); g_qh[i] = h; g_ql[i] = l;
    } else if (i < 4194304u) {
        unsigned j = i - 2097152u;
        float2 v = ((const float2*)(out + OUTN))[j];
        split_pack(v.x, v.y, h, l); g_kh[j] = h; g_kl[j] = l;
    } else {
        unsigned j  = i - 4194304u;                // bh*65536 + d*1024 + jp
        unsigned bh = j >> 16, r = j & 65535u, d = r >> 10, jp = r & 1023u;
        const float* vb = out + KV1 + (size_t)bh * 131072;
        float v0 = vb[(size_t)(2 * jp) * 64 + d];
        float v1 = vb[(size_t)(2 * jp + 1) * 64 + d];
        split_pack(v0, v1, h, l);
        g_vth[j] = h; g_vtl[j] = l;
    }
}

// ---------------------------------------------------------------------------
// Kernel: QKV projection. M=4096, N=3072, Kdim=1024 (512 pairs).
// cp.async double-buffered; 3-term bf16 split mma.
// smem/stage: Ah(2560) Al(2560) Bh(2560) Bl(2560) u32; 2 stages = 81920 B.
// ---------------------------------------------------------------------------
__global__ __launch_bounds__(256, 2) void k_qkv(float* __restrict__ out)
{
    extern __shared__ unsigned sm[];
    const int t = threadIdx.x, warp = t >> 5, lane = t & 31;
    const int wm = warp >> 2, wn = warp & 3;
    const int g = lane >> 2, q = lane & 3;
    const int m0 = blockIdx.y * 128, n0 = blockIdx.x * 128;
    const unsigned smb = (unsigned)__cvta_generic_to_shared(sm);

    float acc[4][4][4];
#pragma unroll
    for (int i = 0; i < 4; i++)
#pragma unroll
        for (int j = 0; j < 4; j++)
#pragma unroll
            for (int c = 0; c < 4; c++) acc[i][j][c] = 0.f;

#define QKV_LOAD(s, ktp)                                                        \
    {                                                                           \
        unsigned base = smb + (s) * 40960;                                      \
        _Pragma("unroll")                                                       \
        for (int i = 0; i < 2; i++) {                                           \
            int c = t + i * 256; int row = c >> 2; int ch = (c & 3) * 4;        \
            unsigned off = (unsigned)(row * 20 + ch) * 4;                       \
            cpa(base + off,         g_xh  + (size_t)(m0 + row) * 512 + (ktp) + ch); \
            cpa(base + 10240 + off, g_xl  + (size_t)(m0 + row) * 512 + (ktp) + ch); \
            cpa(base + 20480 + off, g_wqh + (size_t)(n0 + row) * 512 + (ktp) + ch); \
            cpa(base + 30720 + off, g_wql + (size_t)(n0 + row) * 512 + (ktp) + ch); \
        }                                                                       \
        CP_COMMIT;                                                              \
    }

    QKV_LOAD(0, 0);
    for (int it = 0; it < 32; it++) {
        CP_WAIT0; __syncthreads();
        if (it + 1 < 32) QKV_LOAD((it + 1) & 1, (it + 1) * 16);
        unsigned* base = sm + (it & 1) * 10240;
        unsigned (*Ah)[20] = (unsigned(*)[20])(base);
        unsigned (*Al)[20] = (unsigned(*)[20])(base + 2560);
        unsigned (*Bh)[20] = (unsigned(*)[20])(base + 5120);
        unsigned (*Bl)[20] = (unsigned(*)[20])(base + 7680);
#pragma unroll
        for (int ks = 0; ks < 2; ks++) {
            int kc = ks * 8;
            unsigned ah[4][4], al[4][4];
#pragma unroll
            for (int mi = 0; mi < 4; mi++) {
                int mr = wm * 64 + mi * 16 + g;
                ah[mi][0] = Ah[mr][kc + q];     ah[mi][1] = Ah[mr + 8][kc + q];
                ah[mi][2] = Ah[mr][kc + q + 4]; ah[mi][3] = Ah[mr + 8][kc + q + 4];
                al[mi][0] = Al[mr][kc + q];     al[mi][1] = Al[mr + 8][kc + q];
                al[mi][2] = Al[mr][kc + q + 4]; al[mi][3] = Al[mr + 8][kc + q + 4];
            }
#pragma unroll
            for (int ni = 0; ni < 4; ni++) {
                int nr = wn * 32 + ni * 8 + g;
                unsigned bh0 = Bh[nr][kc + q], bh1 = Bh[nr][kc + q + 4];
                unsigned bl0 = Bl[nr][kc + q], bl1 = Bl[nr][kc + q + 4];
#pragma unroll
                for (int mi = 0; mi < 4; mi++) {
                    mma_bf16(acc[mi][ni], ah[mi][0], ah[mi][1], ah[mi][2], ah[mi][3], bh0, bh1);
                    mma_bf16(acc[mi][ni], ah[mi][0], ah[mi][1], ah[mi][2], ah[mi][3], bl0, bl1);
                    mma_bf16(acc[mi][ni], al[mi][0], al[mi][1], al[mi][2], al[mi][3], bh0, bh1);
                }
            }
        }
        __syncthreads();
    }

#pragma unroll
    for (int mi = 0; mi < 4; mi++) {
#pragma unroll
        for (int cc = 0; cc < 2; cc++) {
            int m  = m0 + wm * 64 + mi * 16 + g + cc * 8;
            int bb = m >> 11;
            int n  = m & 2047;
#pragma unroll
            for (int ni = 0; ni < 4; ni++) {
#pragma unroll
                for (int e = 0; e < 2; e++) {
                    int r = n0 + wn * 32 + ni * 8 + q * 2 + e;
                    float v = acc[mi][ni][cc * 2 + e];
                    int h = r / 192, rem = r - h * 192;
                    int d = rem / 3,  c = rem - d * 3;
                    if (c == 0) {
                        g_Q[(((size_t)(bb * 16 + h)) * 2048 + n) * 64 + d] = v * 0.125f;
                    } else {
                        out[OUTN + (((size_t)((c - 1) * 2 + bb) * 16 + h) * 2048 + n) * 64 + d] = v;
                    }
                }
            }
        }
    }
}

// ---------------------------------------------------------------------------
// Kernel: scores per (b,h). 2048x2048, Kdim=64 (32 pairs) — single-shot tiles.
// smem: Qh[128][36] Ql Kh Kl = 73728 B.
// ---------------------------------------------------------------------------
__global__ __launch_bounds__(256, 2) void k_scores()
{
    extern __shared__ unsigned sm[];
    unsigned (*Qh)[36] = (unsigned(*)[36])(sm);
    unsigned (*Ql)[36] = (unsigned(*)[36])(sm + 4608);
    unsigned (*Kh)[36] = (unsigned(*)[36])(sm + 9216);
    unsigned (*Kl)[36] = (unsigned(*)[36])(sm + 13824);

    const int t = threadIdx.x, warp = t >> 5, lane = t & 31;
    const int wm = warp >> 2, wn = warp & 3;
    const int g = lane >> 2, q = lane & 3;
    const int bh = blockIdx.z;
    const int m0 = blockIdx.y * 128, n0 = blockIdx.x * 128;

#pragma unroll
    for (int i = 0; i < 4; i++) {
        int c = t + i * 256;
        int row = c >> 3, ch = (c & 7) * 4;
        *(uint4*)&Qh[row][ch] = *(const uint4*)(g_qh + ((size_t)bh * 2048 + m0 + row) * 32 + ch);
        *(uint4*)&Ql[row][ch] = *(const uint4*)(g_ql + ((size_t)bh * 2048 + m0 + row) * 32 + ch);
        *(uint4*)&Kh[row][ch] = *(const uint4*)(g_kh + ((size_t)bh * 2048 + n0 + row) * 32 + ch);
        *(uint4*)&Kl[row][ch] = *(const uint4*)(g_kl + ((size_t)bh * 2048 + n0 + row) * 32 + ch);
    }
    __syncthreads();

    float acc[4][4][4];
#pragma unroll
    for (int i = 0; i < 4; i++)
#pragma unroll
        for (int j = 0; j < 4; j++)
#pragma unroll
            for (int c = 0; c < 4; c++) acc[i][j][c] = 0.f;

#pragma unroll
    for (int ks = 0; ks < 4; ks++) {
        int kc = ks * 8;
        unsigned ah[4][4], al[4][4];
#pragma unroll
        for (int mi = 0; mi < 4; mi++) {
            int mr = wm * 64 + mi * 16 + g;
            ah[mi][0] = Qh[mr][kc + q];     ah[mi][1] = Qh[mr + 8][kc + q];
            ah[mi][2] = Qh[mr][kc + q + 4]; ah[mi][3] = Qh[mr + 8][kc + q + 4];
            al[mi][0] = Ql[mr][kc + q];     al[mi][1] = Ql[mr + 8][kc + q];
            al[mi][2] = Ql[mr][kc + q + 4]; al[mi][3] = Ql[mr + 8][kc + q + 4];
        }
#pragma unroll
        for (int ni = 0; ni < 4; ni++) {
            int nr = wn * 32 + ni * 8 + g;
            unsigned bh0 = Kh[nr][kc + q], bh1 = Kh[nr][kc + q + 4];
            unsigned bl0 = Kl[nr][kc + q], bl1 = Kl[nr][kc + q + 4];
#pragma unroll
            for (int mi = 0; mi < 4; mi++) {
                mma_bf16(acc[mi][ni], ah[mi][0], ah[mi][1], ah[mi][2], ah[mi][3], bh0, bh1);
                mma_bf16(acc[mi][ni], ah[mi][0], ah[mi][1], ah[mi][2], ah[mi][3], bl0, bl1);
                mma_bf16(acc[mi][ni], al[mi][0], al[mi][1], al[mi][2], al[mi][3], bh0, bh1);
            }
        }
    }

#pragma unroll
    for (int mi = 0; mi < 4; mi++) {
#pragma unroll
        for (int cc = 0; cc < 2; cc++) {
            int m = m0 + wm * 64 + mi * 16 + g + cc * 8;
            float* Sp = g_S + ((size_t)bh * 2048 + m) * 2048;
#pragma unroll
            for (int ni = 0; ni < 4; ni++) {
                int n = n0 + wn * 32 + ni * 8 + q * 2;
                *(float2*)(Sp + n) = make_float2(acc[mi][ni][cc * 2], acc[mi][ni][cc * 2 + 1]);
            }
        }
    }
}

// ---------------------------------------------------------------------------
// Kernel: fused premix + softmax + postmix. One CTA per (b, i).
// Reads g_S fp32; writes packed attn planes g_ph/g_pl.
// ---------------------------------------------------------------------------
__global__ __launch_bounds__(1024) void k_mix(const float* __restrict__ wpre,
                                              const float* __restrict__ bpre,
                                              const float* __restrict__ wpost,
                                              const float* __restrict__ bpost)
{
    extern __shared__ float smf[];
    float* S   = smf;                // 16*2048
    float* Wa  = smf + 16 * 2048;    // 256
    float* Wb  = Wa + 256;           // 256
    float* ba  = Wb + 256;           // 16
    float* bb2 = ba + 16;            // 16

    const int t  = threadIdx.x;
    const int bi = blockIdx.x;
    const int b  = bi >> 11;
    const int i  = bi & 2047;

    if (t < 256) { Wa[t] = wpre[t]; Wb[t] = wpost[t]; }
    if (t < 16)  { ba[t] = bpre[t]; bb2[t] = bpost[t]; }

    for (int h = 0; h < 16; h++) {
        const float* src = g_S + (((size_t)(b * 16 + h)) * 2048 + i) * 2048;
        float* dst = S + h * 2048;
        for (int j = t * 4; j < 2048; j += 4096)
            *(float4*)(dst + j) = *(const float4*)(src + j);
    }
    __syncthreads();

    // premix
    for (int j = t; j < 2048; j += 1024) {
        float sv[16];
#pragma unroll
        for (int h = 0; h < 16; h++) sv[h] = S[h * 2048 + j];
#pragma unroll
        for (int gg = 0; gg < 16; gg++) {
            float a = ba[gg];
#pragma unroll
            for (int h = 0; h < 16; h++) a += Wa[gg * 16 + h] * sv[h];
            S[gg * 2048 + j] = a;
        }
    }
    __syncthreads();

    // softmax: warps 0..15 each own one head row
    const int w = t >> 5, lane = t & 31;
    if (w < 16) {
        float* row = S + w * 2048;
        float m = -1e30f;
        for (int j = lane; j < 2048; j += 32) m = fmaxf(m, row[j]);
#pragma unroll
        for (int o = 16; o; o >>= 1) m = fmaxf(m, __shfl_xor_sync(0xffffffffu, m, o));
        float z = 0.f;
        for (int j = lane; j < 2048; j += 32) {
            float e = expf(row[j] - m);
            row[j] = e;
            z += e;
        }
#pragma unroll
        for (int o = 16; o; o >>= 1) z += __shfl_xor_sync(0xffffffffu, z, o);
        float inv = 1.f / z;
        for (int j = lane; j < 2048; j += 32) row[j] *= inv;
    }
    __syncthreads();

    // postmix, pack to bf16x2 planes
    {
        int jp = t;                 // 0..1023
        int j  = jp * 2;
        float sv0[16], sv1[16];
#pragma unroll
        for (int h = 0; h < 16; h++) { sv0[h] = S[h * 2048 + j]; sv1[h] = S[h * 2048 + j + 1]; }
#pragma unroll
        for (int gg = 0; gg < 16; gg++) {
            float a0 = bb2[gg], a1 = bb2[gg];
#pragma unroll
            for (int h = 0; h < 16; h++) {
                a0 += Wb[gg * 16 + h] * sv0[h];
                a1 += Wb[gg * 16 + h] * sv1[h];
            }
            unsigned hh, ll;
            split_pack(a0, a1, hh, ll);
            size_t idx = (((size_t)(b * 16 + gg)) * 2048 + i) * 1024 + jp;
            g_ph[idx] = hh; g_pl[idx] = ll;
        }
    }
}

// ---------------------------------------------------------------------------
// Kernel: AV per (b,h). O = P(2048x2048) @ V(2048x64), pipelined.
// smem/stage: Ph(2560) Pl(2560) Vh(1280) Vl(1280) u32; 2 stages = 61440 B.
// Epilogue packs O into g_oh/g_ol (pairs along hd).
// ---------------------------------------------------------------------------
__global__ __launch_bounds__(256, 2) void k_av()
{
    extern __shared__ unsigned sm[];
    const int t = threadIdx.x, warp = t >> 5, lane = t & 31;
    const int wm = warp >> 2, wn = warp & 3;
    const int g = lane >> 2, q = lane & 3;
    const int bh = blockIdx.z;
    const int m0 = blockIdx.y * 128;
    const unsigned smb = (unsigned)__cvta_generic_to_shared(sm);

    float acc[4][2][4];
#pragma unroll
    for (int i = 0; i < 4; i++)
#pragma unroll
        for (int j = 0; j < 2; j++)
#pragma unroll
            for (int c = 0; c < 4; c++) acc[i][j][c] = 0.f;

    const size_t pbase = (size_t)bh * 2048 * 1024;
    const size_t vbase = (size_t)bh * 64 * 1024;

#define AV_LOAD(s, ktp)                                                         \
    {                                                                           \
        unsigned base = smb + (s) * 30720;                                      \
        _Pragma("unroll")                                                       \
        for (int i = 0; i < 2; i++) {                                           \
            int c = t + i * 256; int row = c >> 2; int ch = (c & 3) * 4;        \
            unsigned off = (unsigned)(row * 20 + ch) * 4;                       \
            cpa(base + off,         g_ph + pbase + (size_t)(m0 + row) * 1024 + (ktp) + ch); \
            cpa(base + 10240 + off, g_pl + pbase + (size_t)(m0 + row) * 1024 + (ktp) + ch); \
        }                                                                       \
        {                                                                       \
            int c = t; int row = c >> 2; int ch = (c & 3) * 4;                  \
            unsigned off = (unsigned)(row * 20 + ch) * 4;                       \
            cpa(base + 20480 + off, g_vth + vbase + (size_t)row * 1024 + (ktp) + ch); \
            cpa(base + 25600 + off, g_vtl + vbase + (size_t)row * 1024 + (ktp) + ch); \
        }                                                                       \
        CP_COMMIT;                                                              \
    }

    AV_LOAD(0, 0);
    for (int it = 0; it < 64; it++) {
        CP_WAIT0; __syncthreads();
        if (it + 1 < 64) AV_LOAD((it + 1) & 1, (it + 1) * 16);
        unsigned* base = sm + (it & 1) * 7680;
        unsigned (*Ph)[20] = (unsigned(*)[20])(base);
        unsigned (*Pl)[20] = (unsigned(*)[20])(base + 2560);
        unsigned (*Vh)[20] = (unsigned(*)[20])(base + 5120);
        unsigned (*Vl)[20] = (unsigned(*)[20])(base + 6400);
#pragma unroll
        for (int ks = 0; ks < 2; ks++) {
            int kc = ks * 8;
            unsigned ah[4][4], al[4][4];
#pragma unroll
            for (int mi = 0; mi < 4; mi++) {
                int mr = wm * 64 + mi * 16 + g;
                ah[mi][0] = Ph[mr][kc + q];     ah[mi][1] = Ph[mr + 8][kc + q];
                ah[mi][2] = Ph[mr][kc + q + 4]; ah[mi][3] = Ph[mr + 8][kc + q + 4];
                al[mi][0] = Pl[mr][kc + q];     al[mi][1] = Pl[mr + 8][kc + q];
                al[mi][2] = Pl[mr][kc + q + 4]; al[mi][3] = Pl[mr + 8][kc + q + 4];
            }
#pragma unroll
            for (int ni = 0; ni < 2; ni++) {
                int nr = wn * 16 + ni * 8 + g;
                unsigned bh0 = Vh[nr][kc + q], bh1 = Vh[nr][kc + q + 4];
                unsigned bl0 = Vl[nr][kc + q], bl1 = Vl[nr][kc + q + 4];
#pragma unroll
                for (int mi = 0; mi < 4; mi++) {
                    mma_bf16(acc[mi][ni], ah[mi][0], ah[mi][1], ah[mi][2], ah[mi][3], bh0, bh1);
                    mma_bf16(acc[mi][ni], ah[mi][0], ah[mi][1], ah[mi][2], ah[mi][3], bl0, bl1);
                    mma_bf16(acc[mi][ni], al[mi][0], al[mi][1], al[mi][2], al[mi][3], bh0, bh1);
                }
            }
        }
        __syncthreads();
    }

    const int b = bh >> 4, h = bh & 15;
#pragma unroll
    for (int mi = 0; mi < 4; mi++) {
#pragma unroll
        for (int ni = 0; ni < 2; ni++) {
            int m  = m0 + wm * 64 + mi * 16 + g;
            int dp = h * 32 + wn * 8 + ni * 4 + q;
            unsigned hh, ll;
            split_pack(acc[mi][ni][0], acc[mi][ni][1], hh, ll);
            size_t idx = ((size_t)(b * 2048 + m)) * 512 + dp;
            g_oh[idx] = hh; g_ol[idx] = ll;
            split_pack(acc[mi][ni][2], acc[mi][ni][3], hh, ll);
            idx = ((size_t)(b * 2048 + m + 8)) * 512 + dp;
            g_oh[idx] = hh; g_ol[idx] = ll;
        }
    }
}

// ---------------------------------------------------------------------------
// Kernel: out projection. M=4096, N=1024, Kdim=1024 (512 pairs), pipelined.
// ---------------------------------------------------------------------------
__global__ __launch_bounds__(256, 2) void k_out(float* __restrict__ out)
{
    extern __shared__ unsigned sm[];
    const int t = threadIdx.x, warp = t >> 5, lane = t & 31;
    const int wm = warp >> 2, wn = warp & 3;
    const int g = lane >> 2, q = lane & 3;
    const int m0 = blockIdx.y * 128, n0 = blockIdx.x * 128;
    const unsigned smb = (unsigned)__cvta_generic_to_shared(sm);

    float acc[4][4][4];
#pragma unroll
    for (int i = 0; i < 4; i++)
#pragma unroll
        for (int j = 0; j < 4; j++)
#pragma unroll
            for (int c = 0; c < 4; c++) acc[i][j][c] = 0.f;

#define OUT_LOAD(s, ktp)                                                        \
    {                                                                           \
        unsigned base = smb + (s) * 40960;                                      \
        _Pragma("unroll")                                                       \
        for (int i = 0; i < 2; i++) {                                           \
            int c = t + i * 256; int row = c >> 2; int ch = (c & 3) * 4;        \
            unsigned off = (unsigned)(row * 20 + ch) * 4;                       \
            cpa(base + off,         g_oh  + (size_t)(m0 + row) * 512 + (ktp) + ch); \
            cpa(base + 10240 + off, g_ol  + (size_t)(m0 + row) * 512 + (ktp) + ch); \
            cpa(base + 20480 + off, g_woh + (size_t)(n0 + row) * 512 + (ktp) + ch); \
            cpa(base + 30720 + off, g_wol + (size_t)(n0 + row) * 512 + (ktp) + ch); \
        }                                                                       \
        CP_COMMIT;                                                              \
    }

    OUT_LOAD(0, 0);
    for (int it = 0; it < 32; it++) {
        CP_WAIT0; __syncthreads();
        if (it + 1 < 32) OUT_LOAD((it + 1) & 1, (it + 1) * 16);
        unsigned* base = sm + (it & 1) * 10240;
        unsigned (*Ah)[20] = (unsigned(*)[20])(base);
        unsigned (*Al)[20] = (unsigned(*)[20])(base + 2560);
        unsigned (*Bh)[20] = (unsigned(*)[20])(base + 5120);
        unsigned (*Bl)[20] = (unsigned(*)[20])(base + 7680);
#pragma unroll
        for (int ks = 0; ks < 2; ks++) {
            int kc = ks * 8;
            unsigned ah[4][4], al[4][4];
#pragma unroll
            for (int mi = 0; mi < 4; mi++) {
                int mr = wm * 64 + mi * 16 + g;
                ah[mi][0] = Ah[mr][kc + q];     ah[mi][1] = Ah[mr + 8][kc + q];
                ah[mi][2] = Ah[mr][kc + q + 4]; ah[mi][3] = Ah[mr + 8][kc + q + 4];
                al[mi][0] = Al[mr][kc + q];     al[mi][1] = Al[mr + 8][kc + q];
                al[mi][2] = Al[mr][kc + q + 4]; al[mi][3] = Al[mr + 8][kc + q + 4];
            }
#pragma unroll
            for (int ni = 0; ni < 4; ni++) {
                int nr = wn * 32 + ni * 8 + g;
                unsigned bh0 = Bh[nr][kc + q], bh1 = Bh[nr][kc + q + 4];
                unsigned bl0 = Bl[nr][kc + q], bl1 = Bl[nr][kc + q + 4];
#pragma unroll
                for (int mi = 0; mi < 4; mi++) {
                    mma_bf16(acc[mi][ni], ah[mi][0], ah[mi][1], ah[mi][2], ah[mi][3], bh0, bh1);
                    mma_bf16(acc[mi][ni], ah[mi][0], ah[mi][1], ah[mi][2], ah[mi][3], bl0, bl1);
                    mma_bf16(acc[mi][ni], al[mi][0], al[mi][1], al[mi][2], al[mi][3], bh0, bh1);
                }
            }
        }
        __syncthreads();
    }

#pragma unroll
    for (int mi = 0; mi < 4; mi++) {
#pragma unroll
        for (int cc = 0; cc < 2; cc++) {
            int m = m0 + wm * 64 + mi * 16 + g + cc * 8;
            float* Op = out + (size_t)m * 1024;
#pragma unroll
            for (int ni = 0; ni < 4; ni++) {
                int n = n0 + wn * 32 + ni * 8 + q * 2;
                *(float2*)(Op + n) = make_float2(acc[mi][ni][cc * 2],
                                                 acc[mi][ni][cc * 2 + 1]);
            }
        }
    }
}

// ---------------------------------------------------------------------------
extern "C" void kernel_launch(void* const* d_in, const int* in_sizes, int n_in,
                              void* d_out, int out_size)
{
    const float* x     = (const float*)d_in[0];
    const float* wqkv  = (const float*)d_in[1];
    const float* wout  = (const float*)d_in[2];
    const float* wpre  = (const float*)d_in[3];
    const float* bpre  = (const float*)d_in[4];
    const float* wpost = (const float*)d_in[5];
    const float* bpost = (const float*)d_in[6];
    float* out = (float*)d_out;

    cudaFuncSetAttribute(k_qkv,    cudaFuncAttributeMaxDynamicSharedMemorySize, 81920);
    cudaFuncSetAttribute(k_scores, cudaFuncAttributeMaxDynamicSharedMemorySize, 73728);
    cudaFuncSetAttribute(k_mix,    cudaFuncAttributeMaxDynamicSharedMemorySize, 133248);
    cudaFuncSetAttribute(k_av,     cudaFuncAttributeMaxDynamicSharedMemorySize, 61440);
    cudaFuncSetAttribute(k_out,    cudaFuncAttributeMaxDynamicSharedMemorySize, 81920);

    k_pack_in<<<16384, 256>>>(x, wqkv, wout);
    k_qkv<<<dim3(24, 32), 256, 81920>>>(out);
    k_pack_qkv<<<24576, 256>>>(out);
    k_scores<<<dim3(16, 16, 32), 256, 73728>>>();
    k_mix<<<4096, 1024, 133248>>>(wpre, bpre, wpost, bpost);
    k_av<<<dim3(1, 16, 32), 256, 61440>>>();
    k_out<<<dim3(8, 32), 256, 81920>>>(out);
}